// round 3
// baseline (speedup 1.0000x reference)
#include <cuda_runtime.h>
#include <cuda_bf16.h>
#include <math.h>

// Problem constants
#define B_  4
#define S_  2048
#define D_  1024
#define H_  8
#define DK_ 128
#define NEG_INF_ (-1e9f)

// Scratch (static device globals; allocation-free per harness rules)
__device__ float g_Q[B_ * H_ * S_ * DK_];   // 32 MB each
__device__ float g_K[B_ * H_ * S_ * DK_];
__device__ float g_V[B_ * H_ * S_ * DK_];
__device__ float g_O[B_ * H_ * S_ * DK_];

// ---------------------------------------------------------------------------
// Kernel 1: fused QKV projection GEMM.
// X[8192,1024] @ W[1024,1024] + bias, written head-split to g_{Q,K,V}.
// blockIdx.z selects which of Q/K/V. BM=BN=64, BK=16, 256 threads, 4x4 micro.
// ---------------------------------------------------------------------------
__global__ __launch_bounds__(256) void qkv_proj_kernel(
    const float* __restrict__ Xq, const float* __restrict__ Xk,
    const float* __restrict__ Xv,
    const float* __restrict__ Wq, const float* __restrict__ bq,
    const float* __restrict__ Wk, const float* __restrict__ bk,
    const float* __restrict__ Wv, const float* __restrict__ bv)
{
    const int which = blockIdx.z;
    const float* X    = (which == 0) ? Xq : (which == 1) ? Xk : Xv;
    const float* W    = (which == 0) ? Wq : (which == 1) ? Wk : Wv;
    const float* bias = (which == 0) ? bq : (which == 1) ? bk : bv;
    float* out        = (which == 0) ? g_Q : (which == 1) ? g_K : g_V;

    const int m0 = blockIdx.y * 64;
    const int n0 = blockIdx.x * 64;

    __shared__ float As[16][68];  // As[k][m], padded
    __shared__ float Bs[16][68];  // Bs[k][n], padded

    const int tid = threadIdx.x;
    const int tx  = tid & 15;         // 0..15 -> n micro
    const int ty  = tid >> 4;         // 0..15 -> m micro

    float acc[4][4];
#pragma unroll
    for (int i = 0; i < 4; ++i)
#pragma unroll
        for (int j = 0; j < 4; ++j) acc[i][j] = 0.0f;

    for (int k0 = 0; k0 < D_; k0 += 16) {
        // Load A tile [64 rows m][16 cols k] -> transposed into As[k][m]
        {
            const int r  = tid >> 2;       // 0..63
            const int c4 = tid & 3;        // 0..3 (each = 4 k's)
            const float4 v = *(const float4*)&X[(size_t)(m0 + r) * D_ + k0 + c4 * 4];
            As[c4 * 4 + 0][r] = v.x;
            As[c4 * 4 + 1][r] = v.y;
            As[c4 * 4 + 2][r] = v.z;
            As[c4 * 4 + 3][r] = v.w;
        }
        // Load B tile [16 rows k][64 cols n]
        {
            const int kr = tid >> 4;       // 0..15
            const int c4 = tid & 15;       // 0..15
            const float4 v = *(const float4*)&W[(size_t)(k0 + kr) * D_ + n0 + c4 * 4];
            *(float4*)&Bs[kr][c4 * 4] = v;
        }
        __syncthreads();

#pragma unroll
        for (int k = 0; k < 16; ++k) {
            const float4 a4 = *(const float4*)&As[k][ty * 4];
            const float4 b4 = *(const float4*)&Bs[k][tx * 4];
            const float a[4] = {a4.x, a4.y, a4.z, a4.w};
            const float b[4] = {b4.x, b4.y, b4.z, b4.w};
#pragma unroll
            for (int i = 0; i < 4; ++i)
#pragma unroll
                for (int j = 0; j < 4; ++j)
                    acc[i][j] = fmaf(a[i], b[j], acc[i][j]);
        }
        __syncthreads();
    }

    // Epilogue: bias + head-split store
#pragma unroll
    for (int i = 0; i < 4; ++i) {
        const int m  = m0 + ty * 4 + i;
        const int bb = m / S_;
        const int s  = m - bb * S_;
#pragma unroll
        for (int j = 0; j < 4; ++j) {
            const int n = n0 + tx * 4 + j;
            const int h = n >> 7;          // /128
            const int d = n & 127;
            out[(((size_t)bb * H_ + h) * S_ + s) * DK_ + d] = acc[i][j] + bias[n];
        }
    }
}

// ---------------------------------------------------------------------------
// Kernel 2: causal flash attention, fp32.
// grid = (S/64 q-tiles, B*H). 256 threads. BM=BN=64.
// Smem: Qs[64][132], Ks[64][132], Vs[64][132], Ps[64][68] = 116 KB dynamic.
// ---------------------------------------------------------------------------
#define QK_LD 132
#define PS_LD 68
#define ATTN_SMEM_BYTES ((3 * 64 * QK_LD + 64 * PS_LD) * 4)

__global__ __launch_bounds__(256) void attn_kernel()
{
    extern __shared__ float sm[];
    float* Qs = sm;                       // [64][QK_LD]
    float* Ks = Qs + 64 * QK_LD;
    float* Vs = Ks + 64 * QK_LD;
    float* Ps = Vs + 64 * QK_LD;          // [64][PS_LD]

    const int bh  = blockIdx.y;           // 0..31
    const int qt  = blockIdx.x;           // 0..31
    const int q0  = qt * 64;
    const int tid = threadIdx.x;
    const int tx  = tid & 15;
    const int ty  = tid >> 4;

    const float* Qg = g_Q + (size_t)bh * S_ * DK_;
    const float* Kg = g_K + (size_t)bh * S_ * DK_;
    const float* Vg = g_V + (size_t)bh * S_ * DK_;

    // Load Q tile once (coalesced float4)
    for (int t = tid; t < 64 * 32; t += 256) {
        const int r  = t >> 5;
        const int d4 = t & 31;
        const float4 v = *(const float4*)&Qg[(q0 + r) * DK_ + d4 * 4];
        *(float4*)&Qs[r * QK_LD + d4 * 4] = v;
    }

    const float rs = 0.08838834764831845f;  // 1/sqrt(128)

    float m[4], l[4], o[4][8];
#pragma unroll
    for (int i = 0; i < 4; ++i) { m[i] = -1e30f; l[i] = 0.0f; }
#pragma unroll
    for (int i = 0; i < 4; ++i)
#pragma unroll
        for (int c = 0; c < 8; ++c) o[i][c] = 0.0f;

    for (int kt = 0; kt <= qt; ++kt) {
        const int k0 = kt * 64;
        __syncthreads();  // protect Ks/Vs (prev PV done), Qs (initial load)
        for (int t = tid; t < 64 * 32; t += 256) {
            const int r  = t >> 5;
            const int d4 = t & 31;
            *(float4*)&Ks[r * QK_LD + d4 * 4] =
                *(const float4*)&Kg[(k0 + r) * DK_ + d4 * 4];
            *(float4*)&Vs[r * QK_LD + d4 * 4] =
                *(const float4*)&Vg[(k0 + r) * DK_ + d4 * 4];
        }
        __syncthreads();

        // S tile: 4x4 per thread
        float s[4][4];
#pragma unroll
        for (int i = 0; i < 4; ++i)
#pragma unroll
            for (int j = 0; j < 4; ++j) s[i][j] = 0.0f;

#pragma unroll 4
        for (int d = 0; d < DK_; ++d) {
            float a[4], b[4];
#pragma unroll
            for (int i = 0; i < 4; ++i) a[i] = Qs[(ty * 4 + i) * QK_LD + d];
#pragma unroll
            for (int j = 0; j < 4; ++j) b[j] = Ks[(tx * 4 + j) * QK_LD + d];
#pragma unroll
            for (int i = 0; i < 4; ++i)
#pragma unroll
                for (int j = 0; j < 4; ++j)
                    s[i][j] = fmaf(a[i], b[j], s[i][j]);
        }

        // scale + causal mask (only the diagonal tile needs masking)
#pragma unroll
        for (int i = 0; i < 4; ++i)
#pragma unroll
            for (int j = 0; j < 4; ++j) s[i][j] *= rs;
        if (kt == qt) {
#pragma unroll
            for (int i = 0; i < 4; ++i) {
                const int qrow = q0 + ty * 4 + i;
#pragma unroll
                for (int j = 0; j < 4; ++j) {
                    const int kcol = k0 + tx * 4 + j;
                    if (kcol > qrow) s[i][j] = NEG_INF_;
                }
            }
        }

        // online softmax: row max over 64 cols (16 tx lanes hold 4 each)
        float mnew[4], alpha[4], rsum[4];
#pragma unroll
        for (int i = 0; i < 4; ++i) {
            float mx = fmaxf(fmaxf(s[i][0], s[i][1]), fmaxf(s[i][2], s[i][3]));
#pragma unroll
            for (int w = 8; w >= 1; w >>= 1)
                mx = fmaxf(mx, __shfl_xor_sync(0xffffffffu, mx, w));
            mnew[i]  = fmaxf(m[i], mx);
            alpha[i] = __expf(m[i] - mnew[i]);
            float sum = 0.0f;
#pragma unroll
            for (int j = 0; j < 4; ++j) {
                s[i][j] = __expf(s[i][j] - mnew[i]);
                sum += s[i][j];
            }
#pragma unroll
            for (int w = 8; w >= 1; w >>= 1)
                sum += __shfl_xor_sync(0xffffffffu, sum, w);
            rsum[i] = sum;
        }

#pragma unroll
        for (int i = 0; i < 4; ++i) {
            l[i] = l[i] * alpha[i] + rsum[i];
            m[i] = mnew[i];
#pragma unroll
            for (int c = 0; c < 8; ++c) o[i][c] *= alpha[i];
        }

        // stage P to smem
#pragma unroll
        for (int i = 0; i < 4; ++i)
#pragma unroll
            for (int j = 0; j < 4; ++j)
                Ps[(ty * 4 + i) * PS_LD + tx * 4 + j] = s[i][j];
        __syncthreads();

        // PV: o[i][c] += P[row][k] * V[k][tx + 16*c]
#pragma unroll 2
        for (int k = 0; k < 64; ++k) {
            float p[4], v[8];
#pragma unroll
            for (int i = 0; i < 4; ++i) p[i] = Ps[(ty * 4 + i) * PS_LD + k];
#pragma unroll
            for (int c = 0; c < 8; ++c) v[c] = Vs[k * QK_LD + tx + 16 * c];
#pragma unroll
            for (int i = 0; i < 4; ++i)
#pragma unroll
                for (int c = 0; c < 8; ++c)
                    o[i][c] = fmaf(p[i], v[c], o[i][c]);
        }
    }

    // normalize + store
#pragma unroll
    for (int i = 0; i < 4; ++i) {
        const int row = q0 + ty * 4 + i;
        const float inv = 1.0f / l[i];
#pragma unroll
        for (int c = 0; c < 8; ++c)
            g_O[((size_t)bh * S_ + row) * DK_ + tx + 16 * c] = o[i][c] * inv;
    }
}

// ---------------------------------------------------------------------------
// Kernel 3: merge heads + residual + LayerNorm. One block per (b,s) row.
// ---------------------------------------------------------------------------
__global__ __launch_bounds__(256) void ln_kernel(
    const float* __restrict__ queries,
    const float* __restrict__ gamma,
    const float* __restrict__ beta,
    float* __restrict__ out)
{
    const int row = blockIdx.x;       // b*S + s
    const int bb  = row / S_;
    const int s   = row - bb * S_;
    const int tid = threadIdx.x;

    float v[4];
    float sum = 0.0f, sq = 0.0f;
#pragma unroll
    for (int u = 0; u < 4; ++u) {
        const int n = tid + u * 256;
        const int h = n >> 7;
        const int d = n & 127;
        const float x = g_O[(((size_t)bb * H_ + h) * S_ + s) * DK_ + d]
                      + queries[(size_t)row * D_ + n];
        v[u] = x;
        sum += x;
        sq  += x * x;
    }

    __shared__ float red0[8], red1[8];
#pragma unroll
    for (int w = 16; w >= 1; w >>= 1) {
        sum += __shfl_xor_sync(0xffffffffu, sum, w);
        sq  += __shfl_xor_sync(0xffffffffu, sq,  w);
    }
    const int warp = tid >> 5;
    if ((tid & 31) == 0) { red0[warp] = sum; red1[warp] = sq; }
    __syncthreads();
    if (warp == 0) {
        float a = red0[tid & 7], b = red1[tid & 7];
#pragma unroll
        for (int w = 4; w >= 1; w >>= 1) {
            a += __shfl_xor_sync(0xffffffffu, a, w);
            b += __shfl_xor_sync(0xffffffffu, b, w);
        }
        if (tid == 0) { red0[0] = a; red1[0] = b; }
    }
    __syncthreads();
    const float mu  = red0[0] * (1.0f / D_);
    const float var = red1[0] * (1.0f / D_) - mu * mu;
    const float rstd = rsqrtf(var + 1e-6f);

#pragma unroll
    for (int u = 0; u < 4; ++u) {
        const int n = tid + u * 256;
        out[(size_t)row * D_ + n] = (v[u] - mu) * rstd * gamma[n] + beta[n];
    }
}

// ---------------------------------------------------------------------------
extern "C" void kernel_launch(void* const* d_in, const int* in_sizes, int n_in,
                              void* d_out, int out_size)
{
    const float* queries = (const float*)d_in[0];
    const float* keys    = (const float*)d_in[1];
    const float* values  = (const float*)d_in[2];
    const float* Wq      = (const float*)d_in[3];
    const float* bq      = (const float*)d_in[4];
    const float* Wk      = (const float*)d_in[5];
    const float* bk      = (const float*)d_in[6];
    const float* Wv      = (const float*)d_in[7];
    const float* bv      = (const float*)d_in[8];
    const float* gamma   = (const float*)d_in[9];
    const float* beta    = (const float*)d_in[10];
    float* out = (float*)d_out;

    // 1) QKV projections (grid.z = which)
    dim3 g1(D_ / 64, (B_ * S_) / 64, 3);
    qkv_proj_kernel<<<g1, 256>>>(queries, keys, values, Wq, bq, Wk, bk, Wv, bv);

    // 2) causal flash attention
    cudaFuncSetAttribute(attn_kernel, cudaFuncAttributeMaxDynamicSharedMemorySize,
                         ATTN_SMEM_BYTES);
    dim3 g2(S_ / 64, B_ * H_);
    attn_kernel<<<g2, 256, ATTN_SMEM_BYTES>>>();

    // 3) residual + LayerNorm
    ln_kernel<<<B_ * S_, 256>>>(queries, gamma, beta, out);
}

// round 6
// speedup vs baseline: 3.4939x; 3.4939x over previous
#include <cuda_runtime.h>
#include <cuda_bf16.h>
#include <stdint.h>
#include <math.h>

// Problem constants
#define B_  4
#define S_  2048
#define D_  1024
#define H_  8
#define DK_ 128

// Scratch (static device globals; allocation-free per harness rules)
__device__ float g_Q[B_ * H_ * S_ * DK_];
__device__ float g_K[B_ * H_ * S_ * DK_];
__device__ float g_V[B_ * H_ * S_ * DK_];
__device__ float g_O[B_ * H_ * S_ * DK_];

// ---------------------------------------------------------------------------
// tf32 helpers
// ---------------------------------------------------------------------------
__device__ __forceinline__ uint32_t f2tf32(float x) {
    uint32_t r;
    asm("cvt.rna.tf32.f32 %0, %1;" : "=r"(r) : "f"(x));
    return r;
}

// D += A*B, m16n8k8 tf32. A frag 4 regs, B frag 2 regs, C/D 4 f32.
__device__ __forceinline__ void mma16n8k8(float* c, const uint32_t* a,
                                          const uint32_t* b) {
    asm volatile(
        "mma.sync.aligned.m16n8k8.row.col.f32.tf32.tf32.f32 "
        "{%0,%1,%2,%3}, {%4,%5,%6,%7}, {%8,%9}, {%0,%1,%2,%3};\n"
        : "+f"(c[0]), "+f"(c[1]), "+f"(c[2]), "+f"(c[3])
        : "r"(a[0]), "r"(a[1]), "r"(a[2]), "r"(a[3]), "r"(b[0]), "r"(b[1]));
}

// ---------------------------------------------------------------------------
// Kernel 1: fused QKV projection GEMM, tf32 tensor cores.
// X[8192,1024] @ W[1024,1024] + bias, head-split store to g_{Q,K,V}.
// Block tile 128x128, BK=32, 256 threads = 8 warps (2m x 4n), warp tile 64x32.
// ---------------------------------------------------------------------------
__global__ __launch_bounds__(256) void qkv_proj_kernel(
    const float* __restrict__ Xq, const float* __restrict__ Xk,
    const float* __restrict__ Xv,
    const float* __restrict__ Wq, const float* __restrict__ bq,
    const float* __restrict__ Wk, const float* __restrict__ bk,
    const float* __restrict__ Wv, const float* __restrict__ bv)
{
    const int which = blockIdx.z;
    const float* X    = (which == 0) ? Xq : (which == 1) ? Xk : Xv;
    const float* W    = (which == 0) ? Wq : (which == 1) ? Wk : Wv;
    const float* bias = (which == 0) ? bq : (which == 1) ? bk : bv;
    float* out        = (which == 0) ? g_Q : (which == 1) ? g_K : g_V;

    const int m0 = blockIdx.y * 128;
    const int n0 = blockIdx.x * 128;

    __shared__ uint32_t As[128][36];   // [m][k], ld=36 (== 4 mod 32): A-frag clean
    __shared__ uint32_t Bs[32][136];   // [k][n], ld=136 (== 8 mod 32): B-frag clean

    const int tid  = threadIdx.x;
    const int warp = tid >> 5;
    const int lane = tid & 31;
    const int wm = warp >> 2;          // 0..1
    const int wn = warp & 3;           // 0..3
    const int g  = lane >> 2;          // 0..7
    const int tg = lane & 3;           // 0..3

    float acc[4][4][4];
#pragma unroll
    for (int i = 0; i < 4; ++i)
#pragma unroll
        for (int j = 0; j < 4; ++j)
#pragma unroll
            for (int c = 0; c < 4; ++c) acc[i][j][c] = 0.0f;

    for (int k0 = 0; k0 < D_; k0 += 32) {
        // A tile 128x32
#pragma unroll
        for (int it = 0; it < 4; ++it) {
            const int idx = tid + it * 256;
            const int r  = idx >> 3;
            const int c4 = (idx & 7) * 4;
            const float4 v = *(const float4*)&X[(size_t)(m0 + r) * D_ + k0 + c4];
            uint4 u;
            u.x = f2tf32(v.x); u.y = f2tf32(v.y);
            u.z = f2tf32(v.z); u.w = f2tf32(v.w);
            *(uint4*)&As[r][c4] = u;
        }
        // B tile 32x128
#pragma unroll
        for (int it = 0; it < 4; ++it) {
            const int idx = tid + it * 256;
            const int r  = idx >> 5;
            const int c4 = (idx & 31) * 4;
            const float4 v = *(const float4*)&W[(size_t)(k0 + r) * D_ + n0 + c4];
            uint4 u;
            u.x = f2tf32(v.x); u.y = f2tf32(v.y);
            u.z = f2tf32(v.z); u.w = f2tf32(v.w);
            *(uint4*)&Bs[r][c4] = u;
        }
        __syncthreads();

#pragma unroll
        for (int ks = 0; ks < 4; ++ks) {
            const int kk = ks * 8;
            uint32_t a[4][4], b[4][2];
#pragma unroll
            for (int i = 0; i < 4; ++i) {
                const int rb = wm * 64 + i * 16;
                a[i][0] = As[rb + g][kk + tg];
                a[i][1] = As[rb + g + 8][kk + tg];
                a[i][2] = As[rb + g][kk + tg + 4];
                a[i][3] = As[rb + g + 8][kk + tg + 4];
            }
#pragma unroll
            for (int j = 0; j < 4; ++j) {
                const int cb = wn * 32 + j * 8;
                b[j][0] = Bs[kk + tg][cb + g];
                b[j][1] = Bs[kk + tg + 4][cb + g];
            }
#pragma unroll
            for (int i = 0; i < 4; ++i)
#pragma unroll
                for (int j = 0; j < 4; ++j)
                    mma16n8k8(acc[i][j], a[i], b[j]);
        }
        __syncthreads();
    }

    // Epilogue: bias + head-split store (float2 per c-pair)
#pragma unroll
    for (int i = 0; i < 4; ++i) {
#pragma unroll
        for (int j = 0; j < 4; ++j) {
            const int col = n0 + wn * 32 + j * 8 + tg * 2;
            const int h = col >> 7;
            const int d = col & 127;
            const float b0 = bias[col], b1 = bias[col + 1];
#pragma unroll
            for (int half = 0; half < 2; ++half) {
                const int row = m0 + wm * 64 + i * 16 + g + half * 8;
                const int bb = row >> 11;        // /2048
                const int s  = row & 2047;
                float2 v;
                v.x = acc[i][j][half * 2 + 0] + b0;
                v.y = acc[i][j][half * 2 + 1] + b1;
                *(float2*)&out[(((size_t)bb * H_ + h) * S_ + s) * DK_ + d] = v;
            }
        }
    }
}

// ---------------------------------------------------------------------------
// Kernel 2: causal flash attention, tf32 tensor cores.
// BM=BN=64, dk=128. 256 threads = 8 warps (4m x 2n).
// QK^T: warp tile 16x32 (1 m-frag, 4 n-frags). PV: warp tile 16x64 (8 n-frags).
// ---------------------------------------------------------------------------
#define QS_LD 132   // == 4 mod 32 (A-operand pattern)
#define KS_LD 132   // == 4 mod 32 (B rows = K kv-rows; same access pattern)
#define VS_LD 136   // == 8 mod 32 (B-operand pattern)
#define PS_LD 68    // == 4 mod 32 (A-operand pattern)
#define ATTN_SMEM_WORDS (64*QS_LD + 64*KS_LD + 64*VS_LD + 64*PS_LD + 128 + 128)
#define ATTN_SMEM_BYTES (ATTN_SMEM_WORDS * 4)

__global__ __launch_bounds__(256) void attn_kernel()
{
    extern __shared__ uint32_t smem_u[];
    uint32_t* Qs = smem_u;                 // [64][QS_LD]
    uint32_t* Ks = Qs + 64 * QS_LD;        // [64][KS_LD]  (K tile, kv-row major)
    uint32_t* Vs = Ks + 64 * KS_LD;        // [64][VS_LD]  (V tile, kv-row major)
    uint32_t* Ps = Vs + 64 * VS_LD;        // [64][PS_LD]
    float* redM  = (float*)(Ps + 64 * PS_LD);   // [2][64]
    float* redS  = redM + 128;                  // [2][64]

    const int bh  = blockIdx.y;
    const int qt  = blockIdx.x;
    const int q0  = qt * 64;
    const int tid  = threadIdx.x;
    const int warp = tid >> 5;
    const int lane = tid & 31;
    const int wm = warp >> 1;              // 0..3
    const int wn = warp & 1;               // 0..1
    const int g  = lane >> 2;              // 0..7
    const int tg = lane & 3;               // 0..3
    const int rb = wm * 16;                // warp row base in tile
    const int lr = rb + g;                 // local row (this thread, half 0)

    const float* Qg = g_Q + (size_t)bh * S_ * DK_;
    const float* Kg = g_K + (size_t)bh * S_ * DK_;
    const float* Vg = g_V + (size_t)bh * S_ * DK_;

    // Load Q tile once (convert to tf32)
#pragma unroll
    for (int it = 0; it < 8; ++it) {
        const int idx = tid + it * 256;
        const int r  = idx >> 5;
        const int c4 = (idx & 31) * 4;
        const float4 v = *(const float4*)&Qg[(size_t)(q0 + r) * DK_ + c4];
        uint4 u;
        u.x = f2tf32(v.x); u.y = f2tf32(v.y);
        u.z = f2tf32(v.z); u.w = f2tf32(v.w);
        *(uint4*)&Qs[r * QS_LD + c4] = u;
    }

    const float rs = 0.08838834764831845f;  // 1/sqrt(128)

    float mstate[2] = {-1e30f, -1e30f};
    float lstate[2] = {0.0f, 0.0f};
    float oacc[8][4];
#pragma unroll
    for (int nf = 0; nf < 8; ++nf)
#pragma unroll
        for (int c = 0; c < 4; ++c) oacc[nf][c] = 0.0f;

    for (int kt = 0; kt <= qt; ++kt) {
        const int k0 = kt * 64;
        __syncthreads();   // prev PV done; also covers initial Q load
#pragma unroll
        for (int it = 0; it < 8; ++it) {
            const int idx = tid + it * 256;
            const int r  = idx >> 5;
            const int c4 = (idx & 31) * 4;
            const float4 v = *(const float4*)&Kg[(size_t)(k0 + r) * DK_ + c4];
            uint4 uk;
            uk.x = f2tf32(v.x); uk.y = f2tf32(v.y);
            uk.z = f2tf32(v.z); uk.w = f2tf32(v.w);
            *(uint4*)&Ks[r * KS_LD + c4] = uk;
            const float4 w = *(const float4*)&Vg[(size_t)(k0 + r) * DK_ + c4];
            uint4 uv;
            uv.x = f2tf32(w.x); uv.y = f2tf32(w.y);
            uv.z = f2tf32(w.z); uv.w = f2tf32(w.w);
            *(uint4*)&Vs[r * VS_LD + c4] = uv;
        }
        __syncthreads();

        // ---- S = Q K^T (warp tile 16 x 32) ----
        float sacc[4][4];
#pragma unroll
        for (int j = 0; j < 4; ++j)
#pragma unroll
            for (int c = 0; c < 4; ++c) sacc[j][c] = 0.0f;

#pragma unroll
        for (int ks = 0; ks < 16; ++ks) {
            const int kk = ks * 8;
            uint32_t a[4];
            a[0] = Qs[(rb + g) * QS_LD + kk + tg];
            a[1] = Qs[(rb + g + 8) * QS_LD + kk + tg];
            a[2] = Qs[(rb + g) * QS_LD + kk + tg + 4];
            a[3] = Qs[(rb + g + 8) * QS_LD + kk + tg + 4];
#pragma unroll
            for (int j = 0; j < 4; ++j) {
                const int cb = wn * 32 + j * 8;
                uint32_t b[2];
                b[0] = Ks[(cb + g) * KS_LD + kk + tg];
                b[1] = Ks[(cb + g) * KS_LD + kk + tg + 4];
                mma16n8k8(sacc[j], a, b);
            }
        }

        // scale + causal mask (diag tile only)
        if (kt == qt) {
            const int r0 = q0 + rb + g;
            const int r1 = r0 + 8;
#pragma unroll
            for (int j = 0; j < 4; ++j) {
                const int c0 = k0 + wn * 32 + j * 8 + tg * 2;
                sacc[j][0] = (c0     <= r0) ? sacc[j][0] * rs : -1e30f;
                sacc[j][1] = (c0 + 1 <= r0) ? sacc[j][1] * rs : -1e30f;
                sacc[j][2] = (c0     <= r1) ? sacc[j][2] * rs : -1e30f;
                sacc[j][3] = (c0 + 1 <= r1) ? sacc[j][3] * rs : -1e30f;
            }
        } else {
#pragma unroll
            for (int j = 0; j < 4; ++j)
#pragma unroll
                for (int c = 0; c < 4; ++c) sacc[j][c] *= rs;
        }

        // ---- online softmax ----
        float mx0 = -1e30f, mx1 = -1e30f;
#pragma unroll
        for (int j = 0; j < 4; ++j) {
            mx0 = fmaxf(mx0, fmaxf(sacc[j][0], sacc[j][1]));
            mx1 = fmaxf(mx1, fmaxf(sacc[j][2], sacc[j][3]));
        }
        mx0 = fmaxf(mx0, __shfl_xor_sync(0xffffffffu, mx0, 1));
        mx0 = fmaxf(mx0, __shfl_xor_sync(0xffffffffu, mx0, 2));
        mx1 = fmaxf(mx1, __shfl_xor_sync(0xffffffffu, mx1, 1));
        mx1 = fmaxf(mx1, __shfl_xor_sync(0xffffffffu, mx1, 2));
        if (tg == 0) {
            redM[wn * 64 + lr]     = mx0;
            redM[wn * 64 + lr + 8] = mx1;
        }
        __syncthreads();
        const float tm0 = fmaxf(redM[lr],     redM[64 + lr]);
        const float tm1 = fmaxf(redM[lr + 8], redM[64 + lr + 8]);
        const float mnew0 = fmaxf(mstate[0], tm0);
        const float mnew1 = fmaxf(mstate[1], tm1);
        const float alpha0 = __expf(mstate[0] - mnew0);
        const float alpha1 = __expf(mstate[1] - mnew1);

        float sum0 = 0.0f, sum1 = 0.0f;
#pragma unroll
        for (int j = 0; j < 4; ++j) {
            sacc[j][0] = __expf(sacc[j][0] - mnew0);
            sacc[j][1] = __expf(sacc[j][1] - mnew0);
            sacc[j][2] = __expf(sacc[j][2] - mnew1);
            sacc[j][3] = __expf(sacc[j][3] - mnew1);
            sum0 += sacc[j][0] + sacc[j][1];
            sum1 += sacc[j][2] + sacc[j][3];
        }
        sum0 += __shfl_xor_sync(0xffffffffu, sum0, 1);
        sum0 += __shfl_xor_sync(0xffffffffu, sum0, 2);
        sum1 += __shfl_xor_sync(0xffffffffu, sum1, 1);
        sum1 += __shfl_xor_sync(0xffffffffu, sum1, 2);
        if (tg == 0) {
            redS[wn * 64 + lr]     = sum0;
            redS[wn * 64 + lr + 8] = sum1;
        }

        // write P (tf32) to smem
#pragma unroll
        for (int j = 0; j < 4; ++j) {
            const int pc = wn * 32 + j * 8 + tg * 2;
            uint2 p0, p1;
            p0.x = f2tf32(sacc[j][0]); p0.y = f2tf32(sacc[j][1]);
            p1.x = f2tf32(sacc[j][2]); p1.y = f2tf32(sacc[j][3]);
            *(uint2*)&Ps[lr * PS_LD + pc]       = p0;
            *(uint2*)&Ps[(lr + 8) * PS_LD + pc] = p1;
        }
        __syncthreads();

        lstate[0] = lstate[0] * alpha0 + redS[lr]     + redS[64 + lr];
        lstate[1] = lstate[1] * alpha1 + redS[lr + 8] + redS[64 + lr + 8];
        mstate[0] = mnew0;
        mstate[1] = mnew1;
#pragma unroll
        for (int nf = 0; nf < 8; ++nf) {
            oacc[nf][0] *= alpha0; oacc[nf][1] *= alpha0;
            oacc[nf][2] *= alpha1; oacc[nf][3] *= alpha1;
        }

        // ---- O += P V (warp tile 16 x 64) ----
#pragma unroll
        for (int ks = 0; ks < 8; ++ks) {
            const int kk = ks * 8;
            uint32_t a[4];
            a[0] = Ps[(rb + g) * PS_LD + kk + tg];
            a[1] = Ps[(rb + g + 8) * PS_LD + kk + tg];
            a[2] = Ps[(rb + g) * PS_LD + kk + tg + 4];
            a[3] = Ps[(rb + g + 8) * PS_LD + kk + tg + 4];
#pragma unroll
            for (int nf = 0; nf < 8; ++nf) {
                const int cb = wn * 64 + nf * 8;
                uint32_t b[2];
                b[0] = Vs[(kk + tg) * VS_LD + cb + g];
                b[1] = Vs[(kk + tg + 4) * VS_LD + cb + g];
                mma16n8k8(oacc[nf], a, b);
            }
        }
    }

    // normalize + store
    const float inv0 = 1.0f / lstate[0];
    const float inv1 = 1.0f / lstate[1];
    const int r0 = q0 + rb + g;
#pragma unroll
    for (int nf = 0; nf < 8; ++nf) {
        const int c = wn * 64 + nf * 8 + tg * 2;
        float2 v0, v1;
        v0.x = oacc[nf][0] * inv0; v0.y = oacc[nf][1] * inv0;
        v1.x = oacc[nf][2] * inv1; v1.y = oacc[nf][3] * inv1;
        *(float2*)&g_O[((size_t)bh * S_ + r0) * DK_ + c]     = v0;
        *(float2*)&g_O[((size_t)bh * S_ + r0 + 8) * DK_ + c] = v1;
    }
}

// ---------------------------------------------------------------------------
// Kernel 3: merge heads + residual + LayerNorm. One block per (b,s) row.
// ---------------------------------------------------------------------------
__global__ __launch_bounds__(256) void ln_kernel(
    const float* __restrict__ queries,
    const float* __restrict__ gamma,
    const float* __restrict__ beta,
    float* __restrict__ out)
{
    const int row = blockIdx.x;
    const int bb  = row / S_;
    const int s   = row - bb * S_;
    const int tid = threadIdx.x;

    float v[4];
    float sum = 0.0f, sq = 0.0f;
#pragma unroll
    for (int u = 0; u < 4; ++u) {
        const int n = tid + u * 256;
        const int h = n >> 7;
        const int d = n & 127;
        const float x = g_O[(((size_t)bb * H_ + h) * S_ + s) * DK_ + d]
                      + queries[(size_t)row * D_ + n];
        v[u] = x;
        sum += x;
        sq  += x * x;
    }

    __shared__ float red0[8], red1[8];
#pragma unroll
    for (int w = 16; w >= 1; w >>= 1) {
        sum += __shfl_xor_sync(0xffffffffu, sum, w);
        sq  += __shfl_xor_sync(0xffffffffu, sq,  w);
    }
    const int warp = tid >> 5;
    if ((tid & 31) == 0) { red0[warp] = sum; red1[warp] = sq; }
    __syncthreads();
    if (warp == 0) {
        float a = red0[tid & 7], b = red1[tid & 7];
#pragma unroll
        for (int w = 4; w >= 1; w >>= 1) {
            a += __shfl_xor_sync(0xffffffffu, a, w);
            b += __shfl_xor_sync(0xffffffffu, b, w);
        }
        if (tid == 0) { red0[0] = a; red1[0] = b; }
    }
    __syncthreads();
    const float mu  = red0[0] * (1.0f / D_);
    const float var = red1[0] * (1.0f / D_) - mu * mu;
    const float rstd = rsqrtf(var + 1e-6f);

#pragma unroll
    for (int u = 0; u < 4; ++u) {
        const int n = tid + u * 256;
        out[(size_t)row * D_ + n] = (v[u] - mu) * rstd * gamma[n] + beta[n];
    }
}

// ---------------------------------------------------------------------------
extern "C" void kernel_launch(void* const* d_in, const int* in_sizes, int n_in,
                              void* d_out, int out_size)
{
    const float* queries = (const float*)d_in[0];
    const float* keys    = (const float*)d_in[1];
    const float* values  = (const float*)d_in[2];
    const float* Wq      = (const float*)d_in[3];
    const float* bq      = (const float*)d_in[4];
    const float* Wk      = (const float*)d_in[5];
    const float* bk      = (const float*)d_in[6];
    const float* Wv      = (const float*)d_in[7];
    const float* bv      = (const float*)d_in[8];
    const float* gamma   = (const float*)d_in[9];
    const float* beta    = (const float*)d_in[10];
    float* out = (float*)d_out;

    // 1) QKV projections (grid.z = which)
    dim3 g1(D_ / 128, (B_ * S_) / 128, 3);
    qkv_proj_kernel<<<g1, 256>>>(queries, keys, values, Wq, bq, Wk, bk, Wv, bv);

    // 2) causal flash attention
    cudaFuncSetAttribute(attn_kernel, cudaFuncAttributeMaxDynamicSharedMemorySize,
                         ATTN_SMEM_BYTES);
    dim3 g2(S_ / 64, B_ * H_);
    attn_kernel<<<g2, 256, ATTN_SMEM_BYTES>>>();

    // 3) residual + LayerNorm
    ln_kernel<<<B_ * S_, 256>>>(queries, gamma, beta, out);
}

// round 7
// speedup vs baseline: 7.8480x; 2.2462x over previous
#include <cuda_runtime.h>
#include <cuda_fp16.h>
#include <stdint.h>

#define B_  4
#define S_  2048
#define D_  1024
#define H_  8
#define DK_ 128

// Scratch (static device globals; allocation-free per harness rules)
__device__ __half g_Xh[3][B_ * S_ * D_];     // converted inputs
__device__ __half g_Wh[3][D_ * D_];          // converted weights
__device__ __half g_Qh[B_ * H_ * S_ * DK_];  // Q pre-scaled by 1/sqrt(dk)
__device__ __half g_Kh[B_ * H_ * S_ * DK_];
__device__ __half g_Vh[B_ * H_ * S_ * DK_];
__device__ float  g_O [B_ * H_ * S_ * DK_];

// ---------------------------------------------------------------------------
// PTX helpers
// ---------------------------------------------------------------------------
__device__ __forceinline__ uint32_t smem_u32(const void* p) {
    return (uint32_t)__cvta_generic_to_shared(p);
}
__device__ __forceinline__ void cp16(uint32_t dst, const void* src) {
    asm volatile("cp.async.cg.shared.global [%0], [%1], 16;\n" :: "r"(dst), "l"(src));
}
__device__ __forceinline__ void cp_commit() {
    asm volatile("cp.async.commit_group;\n");
}
template <int N> __device__ __forceinline__ void cp_wait() {
    asm volatile("cp.async.wait_group %0;\n" :: "n"(N));
}
__device__ __forceinline__ void ldsm4(uint32_t& d0, uint32_t& d1, uint32_t& d2,
                                      uint32_t& d3, uint32_t addr) {
    asm volatile("ldmatrix.sync.aligned.m8n8.x4.shared.b16 {%0,%1,%2,%3}, [%4];\n"
                 : "=r"(d0), "=r"(d1), "=r"(d2), "=r"(d3) : "r"(addr));
}
__device__ __forceinline__ void ldsm4t(uint32_t& d0, uint32_t& d1, uint32_t& d2,
                                       uint32_t& d3, uint32_t addr) {
    asm volatile("ldmatrix.sync.aligned.m8n8.x4.trans.shared.b16 {%0,%1,%2,%3}, [%4];\n"
                 : "=r"(d0), "=r"(d1), "=r"(d2), "=r"(d3) : "r"(addr));
}
__device__ __forceinline__ void mma_f16(float* c, uint32_t a0, uint32_t a1,
                                        uint32_t a2, uint32_t a3,
                                        uint32_t b0, uint32_t b1) {
    asm volatile(
        "mma.sync.aligned.m16n8k16.row.col.f32.f16.f16.f32 "
        "{%0,%1,%2,%3}, {%4,%5,%6,%7}, {%8,%9}, {%0,%1,%2,%3};\n"
        : "+f"(c[0]), "+f"(c[1]), "+f"(c[2]), "+f"(c[3])
        : "r"(a0), "r"(a1), "r"(a2), "r"(a3), "r"(b0), "r"(b1));
}
__device__ __forceinline__ uint32_t packh2(float a, float b) {
    __half2 h = __floats2half2_rn(a, b);
    return *(uint32_t*)&h;
}

// ---------------------------------------------------------------------------
// Kernel 0: fp32 -> fp16 convert (X's and W's)
// ---------------------------------------------------------------------------
__global__ __launch_bounds__(256) void cvt_kernel(const float* __restrict__ src,
                                                  int which, int isW, int n4) {
    __half* dst = isW ? g_Wh[which] : g_Xh[which];
    const int i = blockIdx.x * blockDim.x + threadIdx.x;
    if (i < n4) {
        const float4 v = ((const float4*)src)[i];
        __half2* d = (__half2*)dst + (size_t)i * 2;
        d[0] = __floats2half2_rn(v.x, v.y);
        d[1] = __floats2half2_rn(v.z, v.w);
    }
}

// ---------------------------------------------------------------------------
// Kernel 1: QKV projection GEMM, f16 mma + cp.async double buffer.
// Block 128x128, BK=64. 8 warps (2m x 4n), warp 64x32. Q pre-scaled by rs.
// ---------------------------------------------------------------------------
#define PJ_AP 72    // As pitch (halfs): 144B, 144/16=9 (odd) -> ldsm conflict-free
#define PJ_BP 136   // Bs pitch: 272B, /16=17 (odd) -> conflict-free
#define PJ_STAGE (128 * PJ_AP + 64 * PJ_BP)          // halfs per stage
#define PJ_SMEM_BYTES (2 * PJ_STAGE * 2)             // 71680 B

__global__ __launch_bounds__(256, 2) void qkv_proj_kernel(
    const float* __restrict__ bq, const float* __restrict__ bk,
    const float* __restrict__ bv)
{
    const int which = blockIdx.z;
    const __half* X = g_Xh[which];
    const __half* W = g_Wh[which];
    const float* bias = (which == 0) ? bq : (which == 1) ? bk : bv;
    __half* out      = (which == 0) ? g_Qh : (which == 1) ? g_Kh : g_Vh;
    const float oscale = (which == 0) ? 0.08838834764831845f : 1.0f;

    extern __shared__ __half sm[];
    const int m0 = blockIdx.y * 128;
    const int n0 = blockIdx.x * 128;

    const int tid  = threadIdx.x;
    const int warp = tid >> 5;
    const int lane = tid & 31;
    const int wm = warp >> 2, wn = warp & 3;
    const int g  = lane >> 2, tg = lane & 3;

    auto issue = [&](int kt, int st) {
        __half* A = sm + st * PJ_STAGE;
        __half* Bsm = A + 128 * PJ_AP;
        const int k0 = kt * 64;
#pragma unroll
        for (int u = 0; u < 4; ++u) {      // A: 128 rows x 64 halfs
            const int ch = tid + u * 256;
            const int r = ch >> 3, c = ch & 7;
            cp16(smem_u32(A + r * PJ_AP + c * 8),
                 X + (size_t)(m0 + r) * D_ + k0 + c * 8);
        }
#pragma unroll
        for (int u = 0; u < 4; ++u) {      // B: 64 rows x 128 halfs
            const int ch = tid + u * 256;
            const int r = ch >> 4, c = ch & 15;
            cp16(smem_u32(Bsm + r * PJ_BP + c * 8),
                 W + (size_t)(k0 + r) * D_ + n0 + c * 8);
        }
        cp_commit();
    };

    float acc[4][4][4];
#pragma unroll
    for (int i = 0; i < 4; ++i)
#pragma unroll
        for (int j = 0; j < 4; ++j)
#pragma unroll
            for (int c = 0; c < 4; ++c) acc[i][j][c] = 0.0f;

    issue(0, 0);
    issue(1, 1);

    for (int kt = 0; kt < 16; ++kt) {
        cp_wait<1>();
        __syncthreads();
        const __half* A = sm + (kt & 1) * PJ_STAGE;
        const __half* Bsm = A + 128 * PJ_AP;

#pragma unroll
        for (int ks = 0; ks < 4; ++ks) {
            const int kk = ks * 16;
            uint32_t a[4][4];
#pragma unroll
            for (int i = 0; i < 4; ++i) {
                const int row = wm * 64 + i * 16 + (lane & 15);
                const int col = kk + ((lane >> 4) << 3);
                ldsm4(a[i][0], a[i][1], a[i][2], a[i][3],
                      smem_u32(A + row * PJ_AP + col));
            }
#pragma unroll
            for (int jj = 0; jj < 2; ++jj) {
                const int cb = wn * 32 + jj * 16;
                const int krow = kk + (lane & 7) + ((lane & 16) ? 8 : 0);
                const int ncol = cb + (lane & 8);
                uint32_t b00, b01, b10, b11;
                ldsm4t(b00, b01, b10, b11,
                       smem_u32(Bsm + krow * PJ_BP + ncol));
#pragma unroll
                for (int i = 0; i < 4; ++i) {
                    mma_f16(acc[i][jj * 2],     a[i][0], a[i][1], a[i][2], a[i][3], b00, b10);
                    mma_f16(acc[i][jj * 2 + 1], a[i][0], a[i][1], a[i][2], a[i][3], b01, b11);
                }
            }
        }
        __syncthreads();
        if (kt + 2 < 16) issue(kt + 2, kt & 1);
        else cp_commit();   // empty group keeps wait counts consistent
    }

    // Epilogue: bias, optional rs scale, half convert, head-split store
#pragma unroll
    for (int i = 0; i < 4; ++i) {
#pragma unroll
        for (int j = 0; j < 4; ++j) {
            const int col = n0 + wn * 32 + j * 8 + tg * 2;
            const int h = col >> 7, d = col & 127;
            const float b0v = bias[col], b1v = bias[col + 1];
#pragma unroll
            for (int hf = 0; hf < 2; ++hf) {
                const int m = m0 + wm * 64 + i * 16 + g + hf * 8;
                const int bb = m >> 11, s = m & 2047;
                const float v0 = (acc[i][j][hf * 2 + 0] + b0v) * oscale;
                const float v1 = (acc[i][j][hf * 2 + 1] + b1v) * oscale;
                __half2 hv = __floats2half2_rn(v0, v1);
                *(__half2*)&out[(((size_t)bb * H_ + h) * S_ + s) * DK_ + d] = hv;
            }
        }
    }
}

// ---------------------------------------------------------------------------
// Kernel 2: causal flash attention, f16 mma.
// BM=128 (8 warps x 16 rows), BN=64. Warp-local softmax; P stays in registers
// (QK accumulator fragment == PV A fragment). K/V double-buffered cp.async.
// ---------------------------------------------------------------------------
#define AT_P 136                         // pitch (halfs): 272B, /16=17 -> clean
#define AT_QH (128 * AT_P)
#define AT_KVH (64 * AT_P)
#define AT_SMEM_BYTES ((AT_QH + 4 * AT_KVH) * 2)   // 104448 B

__global__ __launch_bounds__(256, 2) void attn_kernel()
{
    extern __shared__ __half sm[];
    __half* Qs  = sm;
    __half* Ks0 = Qs + AT_QH;            // 2 buffers
    __half* Vs0 = Ks0 + 2 * AT_KVH;      // 2 buffers

    const int bh = blockIdx.y;
    const int qt = (int)gridDim.x - 1 - (int)blockIdx.x;  // heavy tiles first
    const int q0 = qt * 128;
    const int tid  = threadIdx.x;
    const int warp = tid >> 5;
    const int lane = tid & 31;
    const int g = lane >> 2, tg = lane & 3;
    const int rb = warp * 16;

    const __half* Qg = g_Qh + (size_t)bh * S_ * DK_;
    const __half* Kg = g_Kh + (size_t)bh * S_ * DK_;
    const __half* Vg = g_Vh + (size_t)bh * S_ * DK_;

    // Prologue: Q tile + K0 + V0
    {
#pragma unroll
        for (int u = 0; u < 8; ++u) {
            const int ch = tid + u * 256;
            const int r = ch >> 4, c = ch & 15;
            cp16(smem_u32(Qs + r * AT_P + c * 8),
                 Qg + (size_t)(q0 + r) * DK_ + c * 8);
        }
#pragma unroll
        for (int u = 0; u < 4; ++u) {
            const int ch = tid + u * 256;
            const int r = ch >> 4, c = ch & 15;
            cp16(smem_u32(Ks0 + r * AT_P + c * 8), Kg + (size_t)r * DK_ + c * 8);
            cp16(smem_u32(Vs0 + r * AT_P + c * 8), Vg + (size_t)r * DK_ + c * 8);
        }
        cp_commit();
    }

    const int nkt = 2 * qt + 2;
    float m0s = -1e30f, m1s = -1e30f, l0 = 0.0f, l1 = 0.0f;
    float oacc[16][4];
#pragma unroll
    for (int j = 0; j < 16; ++j)
#pragma unroll
        for (int c = 0; c < 4; ++c) oacc[j][c] = 0.0f;

    for (int kt = 0; kt < nkt; ++kt) {
        cp_wait<0>();
        __syncthreads();
        const __half* Ksm = Ks0 + (kt & 1) * AT_KVH;
        const __half* Vsm = Vs0 + (kt & 1) * AT_KVH;

        // ---- S = Q K^T : 16 x 64 per warp (Q pre-scaled by 1/sqrt(dk)) ----
        float sacc[8][4];
#pragma unroll
        for (int j = 0; j < 8; ++j)
#pragma unroll
            for (int c = 0; c < 4; ++c) sacc[j][c] = 0.0f;

#pragma unroll
        for (int ks = 0; ks < 8; ++ks) {
            const int kk = ks * 16;
            uint32_t a0, a1, a2, a3;
            {
                const int row = rb + (lane & 15);
                const int col = kk + ((lane >> 4) << 3);
                ldsm4(a0, a1, a2, a3, smem_u32(Qs + row * AT_P + col));
            }
#pragma unroll
            for (int jj = 0; jj < 4; ++jj) {
                const int nrow = jj * 16 + (lane & 15);
                const int col  = kk + ((lane >> 4) << 3);
                uint32_t b00, b01, b10, b11;
                ldsm4(b00, b01, b10, b11, smem_u32(Ksm + nrow * AT_P + col));
                mma_f16(sacc[jj * 2],     a0, a1, a2, a3, b00, b10);
                mma_f16(sacc[jj * 2 + 1], a0, a1, a2, a3, b01, b11);
            }
        }

        // Issue next K tile (overlaps softmax + PV)
        if (kt + 1 < nkt) {
            __half* Kn = Ks0 + ((kt + 1) & 1) * AT_KVH;
            const __half* src = Kg + (size_t)(kt + 1) * 64 * DK_;
#pragma unroll
            for (int u = 0; u < 4; ++u) {
                const int ch = tid + u * 256;
                const int r = ch >> 4, c = ch & 15;
                cp16(smem_u32(Kn + r * AT_P + c * 8), src + (size_t)r * DK_ + c * 8);
            }
        }
        cp_commit();

        // Causal mask (only the last two kv tiles intersect the diagonal)
        if (kt >= 2 * qt) {
            const int k0c = kt * 64;
            const int r0 = q0 + rb + g, r1 = r0 + 8;
#pragma unroll
            for (int j = 0; j < 8; ++j) {
                const int c0 = k0c + j * 8 + tg * 2;
                if (c0     > r0) sacc[j][0] = -1e30f;
                if (c0 + 1 > r0) sacc[j][1] = -1e30f;
                if (c0     > r1) sacc[j][2] = -1e30f;
                if (c0 + 1 > r1) sacc[j][3] = -1e30f;
            }
        }

        // ---- warp-local online softmax (rows g and g+8 of warp tile) ----
        float mx0 = -1e30f, mx1 = -1e30f;
#pragma unroll
        for (int j = 0; j < 8; ++j) {
            mx0 = fmaxf(mx0, fmaxf(sacc[j][0], sacc[j][1]));
            mx1 = fmaxf(mx1, fmaxf(sacc[j][2], sacc[j][3]));
        }
        mx0 = fmaxf(mx0, __shfl_xor_sync(0xffffffffu, mx0, 1));
        mx0 = fmaxf(mx0, __shfl_xor_sync(0xffffffffu, mx0, 2));
        mx1 = fmaxf(mx1, __shfl_xor_sync(0xffffffffu, mx1, 1));
        mx1 = fmaxf(mx1, __shfl_xor_sync(0xffffffffu, mx1, 2));
        const float mn0 = fmaxf(m0s, mx0), mn1 = fmaxf(m1s, mx1);
        const float al0 = __expf(m0s - mn0), al1 = __expf(m1s - mn1);

        float s0 = 0.0f, s1 = 0.0f;
        uint32_t ph[8][2];   // P fragments (half2): exactly the PV A-operand
#pragma unroll
        for (int j = 0; j < 8; ++j) {
            const float p0 = __expf(sacc[j][0] - mn0);
            const float p1 = __expf(sacc[j][1] - mn0);
            const float p2 = __expf(sacc[j][2] - mn1);
            const float p3 = __expf(sacc[j][3] - mn1);
            s0 += p0 + p1;
            s1 += p2 + p3;
            ph[j][0] = packh2(p0, p1);
            ph[j][1] = packh2(p2, p3);
        }
        s0 += __shfl_xor_sync(0xffffffffu, s0, 1);
        s0 += __shfl_xor_sync(0xffffffffu, s0, 2);
        s1 += __shfl_xor_sync(0xffffffffu, s1, 1);
        s1 += __shfl_xor_sync(0xffffffffu, s1, 2);
        l0 = l0 * al0 + s0;
        l1 = l1 * al1 + s1;
        m0s = mn0;
        m1s = mn1;
#pragma unroll
        for (int j = 0; j < 16; ++j) {
            oacc[j][0] *= al0; oacc[j][1] *= al0;
            oacc[j][2] *= al1; oacc[j][3] *= al1;
        }

        // Issue next V tile (overlaps PV)
        if (kt + 1 < nkt) {
            __half* Vn = Vs0 + ((kt + 1) & 1) * AT_KVH;
            const __half* src = Vg + (size_t)(kt + 1) * 64 * DK_;
#pragma unroll
            for (int u = 0; u < 4; ++u) {
                const int ch = tid + u * 256;
                const int r = ch >> 4, c = ch & 15;
                cp16(smem_u32(Vn + r * AT_P + c * 8), src + (size_t)r * DK_ + c * 8);
            }
        }
        cp_commit();

        // ---- O += P V : 16 x 128 per warp, P from registers ----
#pragma unroll
        for (int ks = 0; ks < 4; ++ks) {
            const uint32_t pa0 = ph[2 * ks][0];
            const uint32_t pa1 = ph[2 * ks][1];
            const uint32_t pa2 = ph[2 * ks + 1][0];
            const uint32_t pa3 = ph[2 * ks + 1][1];
            const int kk = ks * 16;
#pragma unroll
            for (int jj = 0; jj < 8; ++jj) {
                const int krow = kk + (lane & 7) + ((lane & 16) ? 8 : 0);
                const int ncol = jj * 16 + (lane & 8);
                uint32_t b00, b01, b10, b11;
                ldsm4t(b00, b01, b10, b11, smem_u32(Vsm + krow * AT_P + ncol));
                mma_f16(oacc[jj * 2],     pa0, pa1, pa2, pa3, b00, b10);
                mma_f16(oacc[jj * 2 + 1], pa0, pa1, pa2, pa3, b01, b11);
            }
        }
    }

    // Epilogue: normalize, store fp32
    const float inv0 = 1.0f / l0, inv1 = 1.0f / l1;
    const int r0 = q0 + rb + g;
    float* Og = g_O + (size_t)bh * S_ * DK_;
#pragma unroll
    for (int j = 0; j < 16; ++j) {
        const int c = j * 8 + tg * 2;
        float2 v0, v1;
        v0.x = oacc[j][0] * inv0; v0.y = oacc[j][1] * inv0;
        v1.x = oacc[j][2] * inv1; v1.y = oacc[j][3] * inv1;
        *(float2*)&Og[(size_t)r0 * DK_ + c] = v0;
        *(float2*)&Og[(size_t)(r0 + 8) * DK_ + c] = v1;
    }
}

// ---------------------------------------------------------------------------
// Kernel 3: merge heads + residual + LayerNorm. One block per (b,s) row.
// ---------------------------------------------------------------------------
__global__ __launch_bounds__(256) void ln_kernel(
    const float* __restrict__ queries,
    const float* __restrict__ gamma,
    const float* __restrict__ beta,
    float* __restrict__ out)
{
    const int row = blockIdx.x;
    const int bb  = row / S_;
    const int s   = row - bb * S_;
    const int tid = threadIdx.x;

    float v[4];
    float sum = 0.0f, sq = 0.0f;
#pragma unroll
    for (int u = 0; u < 4; ++u) {
        const int n = tid + u * 256;
        const int h = n >> 7;
        const int d = n & 127;
        const float x = g_O[(((size_t)bb * H_ + h) * S_ + s) * DK_ + d]
                      + queries[(size_t)row * D_ + n];
        v[u] = x;
        sum += x;
        sq  += x * x;
    }

    __shared__ float red0[8], red1[8];
#pragma unroll
    for (int w = 16; w >= 1; w >>= 1) {
        sum += __shfl_xor_sync(0xffffffffu, sum, w);
        sq  += __shfl_xor_sync(0xffffffffu, sq,  w);
    }
    const int warp = tid >> 5;
    if ((tid & 31) == 0) { red0[warp] = sum; red1[warp] = sq; }
    __syncthreads();
    if (warp == 0) {
        float a = red0[tid & 7], b = red1[tid & 7];
#pragma unroll
        for (int w = 4; w >= 1; w >>= 1) {
            a += __shfl_xor_sync(0xffffffffu, a, w);
            b += __shfl_xor_sync(0xffffffffu, b, w);
        }
        if (tid == 0) { red0[0] = a; red1[0] = b; }
    }
    __syncthreads();
    const float mu   = red0[0] * (1.0f / D_);
    const float var  = red1[0] * (1.0f / D_) - mu * mu;
    const float rstd = rsqrtf(var + 1e-6f);

#pragma unroll
    for (int u = 0; u < 4; ++u) {
        const int n = tid + u * 256;
        out[(size_t)row * D_ + n] = (v[u] - mu) * rstd * gamma[n] + beta[n];
    }
}

// ---------------------------------------------------------------------------
extern "C" void kernel_launch(void* const* d_in, const int* in_sizes, int n_in,
                              void* d_out, int out_size)
{
    const float* queries = (const float*)d_in[0];
    const float* keys    = (const float*)d_in[1];
    const float* values  = (const float*)d_in[2];
    const float* Wq      = (const float*)d_in[3];
    const float* bq      = (const float*)d_in[4];
    const float* Wk      = (const float*)d_in[5];
    const float* bk      = (const float*)d_in[6];
    const float* Wv      = (const float*)d_in[7];
    const float* bv      = (const float*)d_in[8];
    const float* gamma   = (const float*)d_in[9];
    const float* beta    = (const float*)d_in[10];
    float* out = (float*)d_out;

    // 0) convert inputs/weights to fp16
    const int nX4 = (B_ * S_ * D_) / 4;     // 2097152
    const int nW4 = (D_ * D_) / 4;          // 262144
    cvt_kernel<<<(nX4 + 255) / 256, 256>>>(queries, 0, 0, nX4);
    cvt_kernel<<<(nX4 + 255) / 256, 256>>>(keys,    1, 0, nX4);
    cvt_kernel<<<(nX4 + 255) / 256, 256>>>(values,  2, 0, nX4);
    cvt_kernel<<<(nW4 + 255) / 256, 256>>>(Wq, 0, 1, nW4);
    cvt_kernel<<<(nW4 + 255) / 256, 256>>>(Wk, 1, 1, nW4);
    cvt_kernel<<<(nW4 + 255) / 256, 256>>>(Wv, 2, 1, nW4);

    // 1) QKV projections
    cudaFuncSetAttribute(qkv_proj_kernel,
                         cudaFuncAttributeMaxDynamicSharedMemorySize, PJ_SMEM_BYTES);
    dim3 g1(D_ / 128, (B_ * S_) / 128, 3);
    qkv_proj_kernel<<<g1, 256, PJ_SMEM_BYTES>>>(bq, bk, bv);

    // 2) causal flash attention
    cudaFuncSetAttribute(attn_kernel,
                         cudaFuncAttributeMaxDynamicSharedMemorySize, AT_SMEM_BYTES);
    dim3 g2(S_ / 128, B_ * H_);
    attn_kernel<<<g2, 256, AT_SMEM_BYTES>>>();

    // 3) residual + LayerNorm
    ln_kernel<<<B_ * S_, 256>>>(queries, gamma, beta, out);
}

// round 10
// speedup vs baseline: 8.3452x; 1.0634x over previous
#include <cuda_runtime.h>
#include <cuda_fp16.h>
#include <stdint.h>

#define B_  4
#define S_  2048
#define D_  1024
#define H_  8
#define DK_ 128

// Scratch (static device globals; allocation-free per harness rules)
__device__ __half g_Xh[3][B_ * S_ * D_];     // converted inputs
__device__ __half g_Wh[3][D_ * D_];          // converted weights
__device__ __half g_Qh[B_ * H_ * S_ * DK_];  // Q pre-scaled by 1/sqrt(dk)
__device__ __half g_Kh[B_ * H_ * S_ * DK_];
__device__ __half g_Vh[B_ * H_ * S_ * DK_];
__device__ float  g_O [B_ * H_ * S_ * DK_];

// ---------------------------------------------------------------------------
// PTX helpers
// ---------------------------------------------------------------------------
__device__ __forceinline__ uint32_t smem_u32(const void* p) {
    return (uint32_t)__cvta_generic_to_shared(p);
}
__device__ __forceinline__ void cp16(uint32_t dst, const void* src) {
    asm volatile("cp.async.cg.shared.global [%0], [%1], 16;\n" :: "r"(dst), "l"(src));
}
__device__ __forceinline__ void cp_commit() {
    asm volatile("cp.async.commit_group;\n");
}
template <int N> __device__ __forceinline__ void cp_wait() {
    asm volatile("cp.async.wait_group %0;\n" :: "n"(N));
}
__device__ __forceinline__ void ldsm4(uint32_t& d0, uint32_t& d1, uint32_t& d2,
                                      uint32_t& d3, uint32_t addr) {
    asm volatile("ldmatrix.sync.aligned.m8n8.x4.shared.b16 {%0,%1,%2,%3}, [%4];\n"
                 : "=r"(d0), "=r"(d1), "=r"(d2), "=r"(d3) : "r"(addr));
}
__device__ __forceinline__ void ldsm4t(uint32_t& d0, uint32_t& d1, uint32_t& d2,
                                       uint32_t& d3, uint32_t addr) {
    asm volatile("ldmatrix.sync.aligned.m8n8.x4.trans.shared.b16 {%0,%1,%2,%3}, [%4];\n"
                 : "=r"(d0), "=r"(d1), "=r"(d2), "=r"(d3) : "r"(addr));
}
__device__ __forceinline__ void mma_f16(float* c, uint32_t a0, uint32_t a1,
                                        uint32_t a2, uint32_t a3,
                                        uint32_t b0, uint32_t b1) {
    asm volatile(
        "mma.sync.aligned.m16n8k16.row.col.f32.f16.f16.f32 "
        "{%0,%1,%2,%3}, {%4,%5,%6,%7}, {%8,%9}, {%0,%1,%2,%3};\n"
        : "+f"(c[0]), "+f"(c[1]), "+f"(c[2]), "+f"(c[3])
        : "r"(a0), "r"(a1), "r"(a2), "r"(a3), "r"(b0), "r"(b1));
}
__device__ __forceinline__ uint32_t packh2(float a, float b) {
    __half2 h = __floats2half2_rn(a, b);
    return *(uint32_t*)&h;
}

// ---------------------------------------------------------------------------
// Kernel 0: fused fp32 -> fp16 convert. One launch for all 6 tensors.
// Segments (float4 units): 3 X of 2097152, then 3 W of 262144.
// ---------------------------------------------------------------------------
#define CVT_X4 ((B_ * S_ * D_) / 4)   // 2097152
#define CVT_W4 ((D_ * D_) / 4)        // 262144
#define CVT_XBLK (CVT_X4 / 256)       // 8192 blocks per X
#define CVT_WBLK (CVT_W4 / 256)       // 1024 blocks per W
#define CVT_NBLK (3 * CVT_XBLK + 3 * CVT_WBLK)

__global__ __launch_bounds__(256) void cvt_all_kernel(
    const float* __restrict__ q, const float* __restrict__ k,
    const float* __restrict__ v, const float* __restrict__ wq,
    const float* __restrict__ wk, const float* __restrict__ wv)
{
    int blk = blockIdx.x;
    const float* src;
    __half* dst;
    if (blk < 3 * CVT_XBLK) {
        const int which = blk / CVT_XBLK;
        blk -= which * CVT_XBLK;
        src = (which == 0) ? q : (which == 1) ? k : v;
        dst = g_Xh[which];
    } else {
        blk -= 3 * CVT_XBLK;
        const int which = blk / CVT_WBLK;
        blk -= which * CVT_WBLK;
        src = (which == 0) ? wq : (which == 1) ? wk : wv;
        dst = g_Wh[which];
    }
    const int i = blk * 256 + threadIdx.x;
    const float4 x = ((const float4*)src)[i];
    __half2* d = (__half2*)dst + (size_t)i * 2;
    d[0] = __floats2half2_rn(x.x, x.y);
    d[1] = __floats2half2_rn(x.z, x.w);
}

// ---------------------------------------------------------------------------
// Kernel 1: QKV projection GEMM, f16 mma + cp.async double buffer.
// Block 128x128, BK=64. 8 warps (2m x 4n), warp 64x32. Q pre-scaled by rs.
// ---------------------------------------------------------------------------
#define PJ_AP 72
#define PJ_BP 136
#define PJ_STAGE (128 * PJ_AP + 64 * PJ_BP)
#define PJ_SMEM_BYTES (2 * PJ_STAGE * 2)

__global__ __launch_bounds__(256, 2) void qkv_proj_kernel(
    const float* __restrict__ bq, const float* __restrict__ bk,
    const float* __restrict__ bv)
{
    const int which = blockIdx.z;
    const __half* X = g_Xh[which];
    const __half* W = g_Wh[which];
    const float* bias = (which == 0) ? bq : (which == 1) ? bk : bv;
    __half* out      = (which == 0) ? g_Qh : (which == 1) ? g_Kh : g_Vh;
    const float oscale = (which == 0) ? 0.08838834764831845f : 1.0f;

    extern __shared__ __half sm[];
    const int m0 = blockIdx.y * 128;
    const int n0 = blockIdx.x * 128;

    const int tid  = threadIdx.x;
    const int warp = tid >> 5;
    const int lane = tid & 31;
    const int wm = warp >> 2, wn = warp & 3;
    const int g  = lane >> 2, tg = lane & 3;

    auto issue = [&](int kt, int st) {
        __half* A = sm + st * PJ_STAGE;
        __half* Bsm = A + 128 * PJ_AP;
        const int k0 = kt * 64;
#pragma unroll
        for (int u = 0; u < 4; ++u) {
            const int ch = tid + u * 256;
            const int r = ch >> 3, c = ch & 7;
            cp16(smem_u32(A + r * PJ_AP + c * 8),
                 X + (size_t)(m0 + r) * D_ + k0 + c * 8);
        }
#pragma unroll
        for (int u = 0; u < 4; ++u) {
            const int ch = tid + u * 256;
            const int r = ch >> 4, c = ch & 15;
            cp16(smem_u32(Bsm + r * PJ_BP + c * 8),
                 W + (size_t)(k0 + r) * D_ + n0 + c * 8);
        }
        cp_commit();
    };

    float acc[4][4][4];
#pragma unroll
    for (int i = 0; i < 4; ++i)
#pragma unroll
        for (int j = 0; j < 4; ++j)
#pragma unroll
            for (int c = 0; c < 4; ++c) acc[i][j][c] = 0.0f;

    issue(0, 0);
    issue(1, 1);

    for (int kt = 0; kt < 16; ++kt) {
        cp_wait<1>();
        __syncthreads();
        const __half* A = sm + (kt & 1) * PJ_STAGE;
        const __half* Bsm = A + 128 * PJ_AP;

#pragma unroll
        for (int ks = 0; ks < 4; ++ks) {
            const int kk = ks * 16;
            uint32_t a[4][4];
#pragma unroll
            for (int i = 0; i < 4; ++i) {
                const int row = wm * 64 + i * 16 + (lane & 15);
                const int col = kk + ((lane >> 4) << 3);
                ldsm4(a[i][0], a[i][1], a[i][2], a[i][3],
                      smem_u32(A + row * PJ_AP + col));
            }
#pragma unroll
            for (int jj = 0; jj < 2; ++jj) {
                const int cb = wn * 32 + jj * 16;
                const int krow = kk + (lane & 7) + ((lane & 16) ? 8 : 0);
                const int ncol = cb + (lane & 8);
                uint32_t b00, b01, b10, b11;
                ldsm4t(b00, b01, b10, b11,
                       smem_u32(Bsm + krow * PJ_BP + ncol));
#pragma unroll
                for (int i = 0; i < 4; ++i) {
                    mma_f16(acc[i][jj * 2],     a[i][0], a[i][1], a[i][2], a[i][3], b00, b10);
                    mma_f16(acc[i][jj * 2 + 1], a[i][0], a[i][1], a[i][2], a[i][3], b01, b11);
                }
            }
        }
        __syncthreads();
        if (kt + 2 < 16) issue(kt + 2, kt & 1);
        else cp_commit();
    }

#pragma unroll
    for (int i = 0; i < 4; ++i) {
#pragma unroll
        for (int j = 0; j < 4; ++j) {
            const int col = n0 + wn * 32 + j * 8 + tg * 2;
            const int h = col >> 7, d = col & 127;
            const float b0v = bias[col], b1v = bias[col + 1];
#pragma unroll
            for (int hf = 0; hf < 2; ++hf) {
                const int m = m0 + wm * 64 + i * 16 + g + hf * 8;
                const int bb = m >> 11, s = m & 2047;
                const float v0 = (acc[i][j][hf * 2 + 0] + b0v) * oscale;
                const float v1 = (acc[i][j][hf * 2 + 1] + b1v) * oscale;
                __half2 hv = __floats2half2_rn(v0, v1);
                *(__half2*)&out[(((size_t)bb * H_ + h) * S_ + s) * DK_ + d] = hv;
            }
        }
    }
}

// ---------------------------------------------------------------------------
// Kernel 2: causal flash attention, f16 mma.
// 128 threads = 4 warps x 32 q-rows (BM=128), BN=64. Warp-local softmax,
// P in registers, K/V double-buffered cp.async. Halved smem fragment traffic
// vs 8x16 layout.
// ---------------------------------------------------------------------------
#define AT_P 136
#define AT_QH (128 * AT_P)
#define AT_KVH (64 * AT_P)
#define AT_SMEM_BYTES ((AT_QH + 4 * AT_KVH) * 2)   // 104448 B

__global__ __launch_bounds__(128, 2) void attn_kernel()
{
    extern __shared__ __half sm[];
    __half* Qs  = sm;
    __half* Ks0 = Qs + AT_QH;
    __half* Vs0 = Ks0 + 2 * AT_KVH;

    const int bh = blockIdx.y;
    const int qt = (int)gridDim.x - 1 - (int)blockIdx.x;  // heavy tiles first
    const int q0 = qt * 128;
    const int tid  = threadIdx.x;
    const int warp = tid >> 5;
    const int lane = tid & 31;
    const int g = lane >> 2, tg = lane & 3;
    const int wrb = warp * 32;             // warp row base (32 rows per warp)

    const __half* Qg = g_Qh + (size_t)bh * S_ * DK_;
    const __half* Kg = g_Kh + (size_t)bh * S_ * DK_;
    const __half* Vg = g_Vh + (size_t)bh * S_ * DK_;

    // Prologue: Q tile + K0 + V0
    {
#pragma unroll
        for (int u = 0; u < 16; ++u) {
            const int ch = tid + u * 128;
            const int r = ch >> 4, c = ch & 15;
            cp16(smem_u32(Qs + r * AT_P + c * 8),
                 Qg + (size_t)(q0 + r) * DK_ + c * 8);
        }
#pragma unroll
        for (int u = 0; u < 8; ++u) {
            const int ch = tid + u * 128;
            const int r = ch >> 4, c = ch & 15;
            cp16(smem_u32(Ks0 + r * AT_P + c * 8), Kg + (size_t)r * DK_ + c * 8);
            cp16(smem_u32(Vs0 + r * AT_P + c * 8), Vg + (size_t)r * DK_ + c * 8);
        }
        cp_commit();
    }

    const int nkt = 2 * qt + 2;
    float ms[2][2], ls[2][2];
#pragma unroll
    for (int mf = 0; mf < 2; ++mf)
#pragma unroll
        for (int hf = 0; hf < 2; ++hf) { ms[mf][hf] = -1e30f; ls[mf][hf] = 0.0f; }

    float oacc[2][16][4];
#pragma unroll
    for (int mf = 0; mf < 2; ++mf)
#pragma unroll
        for (int j = 0; j < 16; ++j)
#pragma unroll
            for (int c = 0; c < 4; ++c) oacc[mf][j][c] = 0.0f;

    for (int kt = 0; kt < nkt; ++kt) {
        cp_wait<0>();
        __syncthreads();
        const __half* Ksm = Ks0 + (kt & 1) * AT_KVH;
        const __half* Vsm = Vs0 + (kt & 1) * AT_KVH;

        // ---- S = Q K^T : 32 x 64 per warp (Q pre-scaled by 1/sqrt(dk)) ----
        float sacc[2][8][4];
#pragma unroll
        for (int mf = 0; mf < 2; ++mf)
#pragma unroll
            for (int j = 0; j < 8; ++j)
#pragma unroll
                for (int c = 0; c < 4; ++c) sacc[mf][j][c] = 0.0f;

#pragma unroll
        for (int ks = 0; ks < 8; ++ks) {
            const int kk = ks * 16;
            const int col = kk + ((lane >> 4) << 3);
            uint32_t a[2][4];
#pragma unroll
            for (int mf = 0; mf < 2; ++mf) {
                const int row = wrb + mf * 16 + (lane & 15);
                ldsm4(a[mf][0], a[mf][1], a[mf][2], a[mf][3],
                      smem_u32(Qs + row * AT_P + col));
            }
#pragma unroll
            for (int jj = 0; jj < 4; ++jj) {
                const int nrow = jj * 16 + (lane & 15);
                uint32_t b00, b01, b10, b11;
                ldsm4(b00, b01, b10, b11, smem_u32(Ksm + nrow * AT_P + col));
#pragma unroll
                for (int mf = 0; mf < 2; ++mf) {
                    mma_f16(sacc[mf][jj * 2],     a[mf][0], a[mf][1], a[mf][2], a[mf][3], b00, b10);
                    mma_f16(sacc[mf][jj * 2 + 1], a[mf][0], a[mf][1], a[mf][2], a[mf][3], b01, b11);
                }
            }
        }

        // Issue next K tile (overlaps softmax + PV)
        if (kt + 1 < nkt) {
            __half* Kn = Ks0 + ((kt + 1) & 1) * AT_KVH;
            const __half* src = Kg + (size_t)(kt + 1) * 64 * DK_;
#pragma unroll
            for (int u = 0; u < 8; ++u) {
                const int ch = tid + u * 128;
                const int r = ch >> 4, c = ch & 15;
                cp16(smem_u32(Kn + r * AT_P + c * 8), src + (size_t)r * DK_ + c * 8);
            }
        }
        cp_commit();

        // Causal mask (only the last two kv tiles intersect the diagonal)
        if (kt >= 2 * qt) {
            const int k0c = kt * 64;
#pragma unroll
            for (int mf = 0; mf < 2; ++mf) {
                const int r0 = q0 + wrb + mf * 16 + g;
                const int r1 = r0 + 8;
#pragma unroll
                for (int j = 0; j < 8; ++j) {
                    const int c0 = k0c + j * 8 + tg * 2;
                    if (c0     > r0) sacc[mf][j][0] = -1e30f;
                    if (c0 + 1 > r0) sacc[mf][j][1] = -1e30f;
                    if (c0     > r1) sacc[mf][j][2] = -1e30f;
                    if (c0 + 1 > r1) sacc[mf][j][3] = -1e30f;
                }
            }
        }

        // ---- warp-local online softmax ----
        uint32_t ph[2][8][2];
#pragma unroll
        for (int mf = 0; mf < 2; ++mf) {
            float mx0 = -1e30f, mx1 = -1e30f;
#pragma unroll
            for (int j = 0; j < 8; ++j) {
                mx0 = fmaxf(mx0, fmaxf(sacc[mf][j][0], sacc[mf][j][1]));
                mx1 = fmaxf(mx1, fmaxf(sacc[mf][j][2], sacc[mf][j][3]));
            }
            mx0 = fmaxf(mx0, __shfl_xor_sync(0xffffffffu, mx0, 1));
            mx0 = fmaxf(mx0, __shfl_xor_sync(0xffffffffu, mx0, 2));
            mx1 = fmaxf(mx1, __shfl_xor_sync(0xffffffffu, mx1, 1));
            mx1 = fmaxf(mx1, __shfl_xor_sync(0xffffffffu, mx1, 2));
            const float mn0 = fmaxf(ms[mf][0], mx0);
            const float mn1 = fmaxf(ms[mf][1], mx1);
            const float al0 = __expf(ms[mf][0] - mn0);
            const float al1 = __expf(ms[mf][1] - mn1);

            float s0 = 0.0f, s1 = 0.0f;
#pragma unroll
            for (int j = 0; j < 8; ++j) {
                const float p0 = __expf(sacc[mf][j][0] - mn0);
                const float p1 = __expf(sacc[mf][j][1] - mn0);
                const float p2 = __expf(sacc[mf][j][2] - mn1);
                const float p3 = __expf(sacc[mf][j][3] - mn1);
                s0 += p0 + p1;
                s1 += p2 + p3;
                ph[mf][j][0] = packh2(p0, p1);
                ph[mf][j][1] = packh2(p2, p3);
            }
            s0 += __shfl_xor_sync(0xffffffffu, s0, 1);
            s0 += __shfl_xor_sync(0xffffffffu, s0, 2);
            s1 += __shfl_xor_sync(0xffffffffu, s1, 1);
            s1 += __shfl_xor_sync(0xffffffffu, s1, 2);
            ls[mf][0] = ls[mf][0] * al0 + s0;
            ls[mf][1] = ls[mf][1] * al1 + s1;
            ms[mf][0] = mn0;
            ms[mf][1] = mn1;
#pragma unroll
            for (int j = 0; j < 16; ++j) {
                oacc[mf][j][0] *= al0; oacc[mf][j][1] *= al0;
                oacc[mf][j][2] *= al1; oacc[mf][j][3] *= al1;
            }
        }

        // Issue next V tile (overlaps PV)
        if (kt + 1 < nkt) {
            __half* Vn = Vs0 + ((kt + 1) & 1) * AT_KVH;
            const __half* src = Vg + (size_t)(kt + 1) * 64 * DK_;
#pragma unroll
            for (int u = 0; u < 8; ++u) {
                const int ch = tid + u * 128;
                const int r = ch >> 4, c = ch & 15;
                cp16(smem_u32(Vn + r * AT_P + c * 8), src + (size_t)r * DK_ + c * 8);
            }
        }
        cp_commit();

        // ---- O += P V : 32 x 128 per warp, P from registers ----
#pragma unroll
        for (int ks = 0; ks < 4; ++ks) {
            const int kk = ks * 16;
#pragma unroll
            for (int jj = 0; jj < 8; ++jj) {
                const int krow = kk + (lane & 7) + ((lane & 16) ? 8 : 0);
                const int ncol = jj * 16 + (lane & 8);
                uint32_t b00, b01, b10, b11;
                ldsm4t(b00, b01, b10, b11, smem_u32(Vsm + krow * AT_P + ncol));
#pragma unroll
                for (int mf = 0; mf < 2; ++mf) {
                    mma_f16(oacc[mf][jj * 2],
                            ph[mf][2 * ks][0], ph[mf][2 * ks][1],
                            ph[mf][2 * ks + 1][0], ph[mf][2 * ks + 1][1], b00, b10);
                    mma_f16(oacc[mf][jj * 2 + 1],
                            ph[mf][2 * ks][0], ph[mf][2 * ks][1],
                            ph[mf][2 * ks + 1][0], ph[mf][2 * ks + 1][1], b01, b11);
                }
            }
        }
    }

    // Epilogue: normalize, store fp32
    float* Og = g_O + (size_t)bh * S_ * DK_;
#pragma unroll
    for (int mf = 0; mf < 2; ++mf) {
        const float inv0 = 1.0f / ls[mf][0];
        const float inv1 = 1.0f / ls[mf][1];
        const int r0 = q0 + wrb + mf * 16 + g;
#pragma unroll
        for (int j = 0; j < 16; ++j) {
            const int c = j * 8 + tg * 2;
            float2 v0, v1;
            v0.x = oacc[mf][j][0] * inv0; v0.y = oacc[mf][j][1] * inv0;
            v1.x = oacc[mf][j][2] * inv1; v1.y = oacc[mf][j][3] * inv1;
            *(float2*)&Og[(size_t)r0 * DK_ + c] = v0;
            *(float2*)&Og[(size_t)(r0 + 8) * DK_ + c] = v1;
        }
    }
}

// ---------------------------------------------------------------------------
// Kernel 3: merge heads + residual + LayerNorm. One block per (b,s) row.
// ---------------------------------------------------------------------------
__global__ __launch_bounds__(256) void ln_kernel(
    const float* __restrict__ queries,
    const float* __restrict__ gamma,
    const float* __restrict__ beta,
    float* __restrict__ out)
{
    const int row = blockIdx.x;
    const int bb  = row / S_;
    const int s   = row - bb * S_;
    const int tid = threadIdx.x;

    float v[4];
    float sum = 0.0f, sq = 0.0f;
#pragma unroll
    for (int u = 0; u < 4; ++u) {
        const int n = tid + u * 256;
        const int h = n >> 7;
        const int d = n & 127;
        const float x = g_O[(((size_t)bb * H_ + h) * S_ + s) * DK_ + d]
                      + queries[(size_t)row * D_ + n];
        v[u] = x;
        sum += x;
        sq  += x * x;
    }

    __shared__ float red0[8], red1[8];
#pragma unroll
    for (int w = 16; w >= 1; w >>= 1) {
        sum += __shfl_xor_sync(0xffffffffu, sum, w);
        sq  += __shfl_xor_sync(0xffffffffu, sq,  w);
    }
    const int warp = tid >> 5;
    if ((tid & 31) == 0) { red0[warp] = sum; red1[warp] = sq; }
    __syncthreads();
    if (warp == 0) {
        float a = red0[tid & 7], b = red1[tid & 7];
#pragma unroll
        for (int w = 4; w >= 1; w >>= 1) {
            a += __shfl_xor_sync(0xffffffffu, a, w);
            b += __shfl_xor_sync(0xffffffffu, b, w);
        }
        if (tid == 0) { red0[0] = a; red1[0] = b; }
    }
    __syncthreads();
    const float mu   = red0[0] * (1.0f / D_);
    const float var  = red1[0] * (1.0f / D_) - mu * mu;
    const float rstd = rsqrtf(var + 1e-6f);

#pragma unroll
    for (int u = 0; u < 4; ++u) {
        const int n = tid + u * 256;
        out[(size_t)row * D_ + n] = (v[u] - mu) * rstd * gamma[n] + beta[n];
    }
}

// ---------------------------------------------------------------------------
extern "C" void kernel_launch(void* const* d_in, const int* in_sizes, int n_in,
                              void* d_out, int out_size)
{
    const float* queries = (const float*)d_in[0];
    const float* keys    = (const float*)d_in[1];
    const float* values  = (const float*)d_in[2];
    const float* Wq      = (const float*)d_in[3];
    const float* bq      = (const float*)d_in[4];
    const float* Wk      = (const float*)d_in[5];
    const float* bk      = (const float*)d_in[6];
    const float* Wv      = (const float*)d_in[7];
    const float* bv      = (const float*)d_in[8];
    const float* gamma   = (const float*)d_in[9];
    const float* beta    = (const float*)d_in[10];
    float* out = (float*)d_out;

    // 0) fused convert (single launch)
    cvt_all_kernel<<<CVT_NBLK, 256>>>(queries, keys, values, Wq, Wk, Wv);

    // 1) QKV projections
    cudaFuncSetAttribute(qkv_proj_kernel,
                         cudaFuncAttributeMaxDynamicSharedMemorySize, PJ_SMEM_BYTES);
    dim3 g1(D_ / 128, (B_ * S_) / 128, 3);
    qkv_proj_kernel<<<g1, 256, PJ_SMEM_BYTES>>>(bq, bk, bv);

    // 2) causal flash attention
    cudaFuncSetAttribute(attn_kernel,
                         cudaFuncAttributeMaxDynamicSharedMemorySize, AT_SMEM_BYTES);
    dim3 g2(S_ / 128, B_ * H_);
    attn_kernel<<<g2, 128, AT_SMEM_BYTES>>>();

    // 3) residual + LayerNorm
    ln_kernel<<<B_ * S_, 256>>>(queries, gamma, beta, out);
}